// round 1
// baseline (speedup 1.0000x reference)
#include <cuda_runtime.h>
#include <cuda_bf16.h>
#include <math.h>

// ---------------------------------------------------------------------------
// ParallelTransformerBlock: B=1, N=2048, DIM=2048, HEADS=16, DH=128,
// ATTN_INNER=2048, FF_INNER=8192, FUSED_OUT=18688, EPS=1e-5
//
// Pipeline:
//   1. LayerNorm(x)*gamma -> g_xn
//   2. g_proj = g_xn @ w_fused               [2048 x 18688]
//   3. sim_h  = scale * Q_h @ K^T (causal tile-skip)   per head
//   4. causal softmax rows (zeros above diagonal)
//   5. attn_h = P_h @ V   -> g_attnc (concat heads)
//   6. g_ffact = silu(gate) * ff_x
//   7. d_out  = g_attnc @ w_attn_out
//   8. d_out += g_ffact @ w_ff_out
// ---------------------------------------------------------------------------

#define NSEQ 2048
#define DIM 2048
#define DH 128
#define HEADS 16
#define ATTN_INNER 2048
#define FF_INNER 8192
#define FUSED_OUT 18688
#define FF_BASE 2304      // ATTN_INNER + 2*DH
#define GATE_BASE 10496   // FF_BASE + FF_INNER
#define LN_EPS 1e-5f

// ------------------------- device scratch (static) -------------------------
__device__ float g_xn[(size_t)NSEQ * DIM];                    // 16 MB
__device__ float g_proj[(size_t)NSEQ * FUSED_OUT];            // 153 MB
__device__ float g_sim[(size_t)HEADS * NSEQ * NSEQ];          // 256 MB
__device__ float g_attnc[(size_t)NSEQ * ATTN_INNER];          // 16 MB
__device__ float g_ffact[(size_t)NSEQ * FF_INNER];            // 64 MB

// ------------------------------ LayerNorm ----------------------------------
__global__ __launch_bounds__(256) void ln_kernel(const float* __restrict__ x,
                                                 const float* __restrict__ gamma) {
    int row = blockIdx.x;
    int tid = threadIdx.x;
    const float* xr = x + (size_t)row * DIM;
    float* out = g_xn + (size_t)row * DIM;

    float s = 0.f, sq = 0.f;
    #pragma unroll
    for (int j = tid; j < DIM; j += 256) {
        float v = xr[j];
        s += v;
        sq += v * v;
    }
    __shared__ float red[256];
    __shared__ float red2[256];
    red[tid] = s; red2[tid] = sq;
    __syncthreads();
    for (int off = 128; off > 0; off >>= 1) {
        if (tid < off) { red[tid] += red[tid + off]; red2[tid] += red2[tid + off]; }
        __syncthreads();
    }
    float mu = red[0] * (1.0f / DIM);
    float var = red2[0] * (1.0f / DIM) - mu * mu;
    float inv = rsqrtf(var + LN_EPS);
    #pragma unroll
    for (int j = tid; j < DIM; j += 256) {
        out[j] = (xr[j] - mu) * inv * gamma[j];
    }
}

// ------------------------------- SGEMM -------------------------------------
// C[M,N] (+)= alpha * A[M,K] @ op(B);  op(B)=B [K,N] (NN) or B^T with B [N,K] (NT).
// All dims assumed divisible by 128 (M,N) and 16 (K) -- true for every call here.
template <bool TRANSB, bool ACCUM, bool CAUSAL_SKIP>
__global__ __launch_bounds__(256) void sgemm(
    const float* __restrict__ A, long long lda, long long strideA,
    const float* __restrict__ B, long long ldb, long long strideB,
    float* __restrict__ C, long long ldc, long long strideC,
    int M, int N, int K, float alpha)
{
    constexpr int BM = 128, BN = 128, BK = 16, TM = 8, TN = 8;
    int bx = blockIdx.x;            // N tile
    int by = blockIdx.y;            // M tile
    if (CAUSAL_SKIP && bx > by) return;   // entire tile above diagonal
    int bz = blockIdx.z;

    A += (size_t)bz * strideA;
    B += (size_t)bz * strideB;
    C += (size_t)bz * strideC;

    const int m0 = by * BM;
    const int n0 = bx * BN;
    const int tid = threadIdx.x;
    const int tRow = tid / (BN / TN);   // 0..15
    const int tCol = tid % (BN / TN);   // 0..15

    __shared__ float As[BK][BM];
    __shared__ float Bs[BK][BN + 4];

    float acc[TM][TN];
    #pragma unroll
    for (int i = 0; i < TM; i++)
        #pragma unroll
        for (int j = 0; j < TN; j++) acc[i][j] = 0.f;

    for (int kk = 0; kk < K; kk += BK) {
        // load A tile (BM x BK) -> As[k][m]
        #pragma unroll
        for (int i = tid; i < BM * BK; i += 256) {
            int m = i >> 4;
            int k = i & 15;
            As[k][m] = A[(long long)(m0 + m) * lda + (kk + k)];
        }
        // load B tile -> Bs[k][n]
        if (!TRANSB) {
            #pragma unroll
            for (int i = tid; i < BK * BN; i += 256) {
                int k = i >> 7;
                int n = i & 127;
                Bs[k][n] = B[(long long)(kk + k) * ldb + (n0 + n)];
            }
        } else {
            #pragma unroll
            for (int i = tid; i < BK * BN; i += 256) {
                int n = i >> 4;
                int k = i & 15;
                Bs[k][n] = B[(long long)(n0 + n) * ldb + (kk + k)];
            }
        }
        __syncthreads();

        #pragma unroll
        for (int k = 0; k < BK; k++) {
            float a[TM], b[TN];
            #pragma unroll
            for (int i = 0; i < TM; i++) a[i] = As[k][tRow * TM + i];
            #pragma unroll
            for (int j = 0; j < TN; j++) b[j] = Bs[k][tCol * TN + j];
            #pragma unroll
            for (int i = 0; i < TM; i++)
                #pragma unroll
                for (int j = 0; j < TN; j++)
                    acc[i][j] = fmaf(a[i], b[j], acc[i][j]);
        }
        __syncthreads();
    }

    #pragma unroll
    for (int i = 0; i < TM; i++) {
        int m = m0 + tRow * TM + i;
        float* crow = C + (long long)m * ldc + n0 + tCol * TN;
        #pragma unroll
        for (int j = 0; j < TN; j++) {
            float v = alpha * acc[i][j];
            if (ACCUM) v += crow[j];
            crow[j] = v;
        }
    }
}

// ------------------------ causal softmax (in place) -------------------------
__global__ __launch_bounds__(256) void softmax_causal(void) {
    int i = blockIdx.x;       // query row
    int h = blockIdx.y;       // head
    float* row = g_sim + ((size_t)h * NSEQ + i) * NSEQ;
    int L = i + 1;
    int tid = threadIdx.x;

    __shared__ float red[256];

    float m = -INFINITY;
    for (int j = tid; j < L; j += 256) m = fmaxf(m, row[j]);
    red[tid] = m;
    __syncthreads();
    for (int off = 128; off > 0; off >>= 1) {
        if (tid < off) red[tid] = fmaxf(red[tid], red[tid + off]);
        __syncthreads();
    }
    m = red[0];
    __syncthreads();

    float s = 0.f;
    for (int j = tid; j < L; j += 256) {
        float e = expf(row[j] - m);
        row[j] = e;
        s += e;
    }
    red[tid] = s;
    __syncthreads();
    for (int off = 128; off > 0; off >>= 1) {
        if (tid < off) red[tid] += red[tid + off];
        __syncthreads();
    }
    float inv = 1.0f / red[0];

    for (int j = tid; j < L; j += 256) row[j] *= inv;
    for (int j = L + tid; j < NSEQ; j += 256) row[j] = 0.f;  // exact zeros for PV GEMM
}

// --------------------------- SwiGLU activation ------------------------------
__global__ __launch_bounds__(256) void ff_act_kernel(void) {
    size_t total = (size_t)NSEQ * FF_INNER;
    for (size_t idx = (size_t)blockIdx.x * blockDim.x + threadIdx.x;
         idx < total; idx += (size_t)gridDim.x * blockDim.x) {
        size_t i = idx / FF_INNER;
        size_t j = idx % FF_INNER;
        const float* prow = g_proj + i * FUSED_OUT;
        float xv = prow[FF_BASE + j];
        float g  = prow[GATE_BASE + j];
        float sg = g / (1.0f + expf(-g));   // silu
        g_ffact[idx] = sg * xv;
    }
}

// ------------------------------- launch -------------------------------------
extern "C" void kernel_launch(void* const* d_in, const int* in_sizes, int n_in,
                              void* d_out, int out_size) {
    const float* x          = (const float*)d_in[0];
    const float* gamma      = (const float*)d_in[1];
    const float* w_fused    = (const float*)d_in[2];
    const float* w_attn_out = (const float*)d_in[3];
    const float* w_ff_out   = (const float*)d_in[4];
    float* out = (float*)d_out;

    // resolve device globals
    float *p_xn, *p_proj, *p_sim, *p_attnc, *p_ffact;
    cudaGetSymbolAddress((void**)&p_xn, g_xn);
    cudaGetSymbolAddress((void**)&p_proj, g_proj);
    cudaGetSymbolAddress((void**)&p_sim, g_sim);
    cudaGetSymbolAddress((void**)&p_attnc, g_attnc);
    cudaGetSymbolAddress((void**)&p_ffact, g_ffact);

    const float scale = 0.08838834764831845f;  // 128^-0.5

    // 1. LayerNorm
    ln_kernel<<<NSEQ, 256>>>(x, gamma);

    // 2. fused projection: proj = xn @ w_fused   [2048x2048]x[2048x18688]
    sgemm<false, false, false><<<dim3(FUSED_OUT / 128, NSEQ / 128, 1), 256>>>(
        p_xn, DIM, 0, w_fused, FUSED_OUT, 0, p_proj, FUSED_OUT, 0,
        NSEQ, FUSED_OUT, DIM, 1.0f);

    // 3. sim_h = scale * Q_h @ K^T   (NT, per-head batch, skip upper tiles)
    sgemm<true, false, true><<<dim3(NSEQ / 128, NSEQ / 128, HEADS), 256>>>(
        p_proj, FUSED_OUT, DH,                      // A: Q_h = proj[:, h*128 : h*128+128]
        p_proj + ATTN_INNER, FUSED_OUT, 0,          // B: K = proj[:, 2048:2176], as [N,K]
        p_sim, NSEQ, (long long)NSEQ * NSEQ,
        NSEQ, NSEQ, DH, scale);

    // 4. causal softmax
    softmax_causal<<<dim3(NSEQ, HEADS), 256>>>();

    // 5. attn_h = P_h @ V  -> concat into g_attnc
    sgemm<false, false, false><<<dim3(1, NSEQ / 128, HEADS), 256>>>(
        p_sim, NSEQ, (long long)NSEQ * NSEQ,
        p_proj + ATTN_INNER + DH, FUSED_OUT, 0,     // V = proj[:, 2176:2304]
        p_attnc, ATTN_INNER, DH,
        NSEQ, DH, NSEQ, 1.0f);

    // 6. SwiGLU activation
    ff_act_kernel<<<2048, 256>>>();

    // 7. out = attnc @ w_attn_out
    sgemm<false, false, false><<<dim3(DIM / 128, NSEQ / 128, 1), 256>>>(
        p_attnc, ATTN_INNER, 0, w_attn_out, DIM, 0, out, DIM, 0,
        NSEQ, DIM, ATTN_INNER, 1.0f);

    // 8. out += ffact @ w_ff_out
    sgemm<false, true, false><<<dim3(DIM / 128, NSEQ / 128, 1), 256>>>(
        p_ffact, FF_INNER, 0, w_ff_out, DIM, 0, out, DIM, 0,
        NSEQ, DIM, FF_INNER, 1.0f);
}

// round 5
// speedup vs baseline: 4.4019x; 4.4019x over previous
#include <cuda_runtime.h>
#include <cuda_bf16.h>
#include <cstdint>
#include <math.h>

// ---------------------------------------------------------------------------
// ParallelTransformerBlock via legacy tensor-core path (mma.sync tf32 + cp.async)
// B=1, N=2048, DIM=2048, HEADS=16, DH=128, FF_INNER=8192, FUSED_OUT=18688
// (tcgen05 is unavailable: harness targets compute_103 without the 'a' feature)
// ---------------------------------------------------------------------------

#define NSEQ 2048
#define DIM 2048
#define DH 128
#define HEADS 16
#define ATTN_INNER 2048
#define FF_INNER 8192
#define FUSED_OUT 18688
#define FF_BASE 2304      // ATTN_INNER + 2*DH
#define GATE_BASE 10496   // FF_BASE + FF_INNER
#define LN_EPS 1e-5f

// ------------------------- device scratch (static) -------------------------
__device__ float g_xn[(size_t)NSEQ * DIM];                    // 16 MB
__device__ float g_proj[(size_t)NSEQ * FUSED_OUT];            // 153 MB
__device__ float g_sim[(size_t)HEADS * NSEQ * NSEQ];          // 256 MB
__device__ float g_attnc[(size_t)NSEQ * ATTN_INNER];          // 16 MB
__device__ float g_ffact[(size_t)NSEQ * FF_INNER];            // 64 MB
// tf32-rounded weight copies
__device__ float g_wf[(size_t)DIM * FUSED_OUT];               // 153 MB
__device__ float g_wao[(size_t)ATTN_INNER * DIM];             // 16 MB
__device__ float g_wfo[(size_t)FF_INNER * DIM];               // 64 MB

// --------------------------- PTX helpers -----------------------------------
__device__ __forceinline__ uint32_t smem_u32(const void* p) {
    uint32_t a;
    asm("{ .reg .u64 t; cvta.to.shared.u64 t, %1; cvt.u32.u64 %0, t; }"
        : "=r"(a) : "l"(p));
    return a;
}

__device__ __forceinline__ float tf32r(float x) {
    uint32_t u;
    asm("cvt.rna.tf32.f32 %0, %1;" : "=r"(u) : "f"(x));
    return __uint_as_float(u);
}

#define CP_ASYNC16(smaddr, gptr) \
    asm volatile("cp.async.cg.shared.global [%0], [%1], 16;" :: "r"(smaddr), "l"(gptr))
#define CP_COMMIT() asm volatile("cp.async.commit_group;" ::: "memory")
#define CP_WAIT2()  asm volatile("cp.async.wait_group 2;" ::: "memory")

__device__ __forceinline__ void mma1688(float* d, const uint32_t* a, const uint32_t* b) {
    asm volatile(
        "mma.sync.aligned.m16n8k8.row.col.f32.tf32.tf32.f32 "
        "{%0,%1,%2,%3}, {%4,%5,%6,%7}, {%8,%9}, {%0,%1,%2,%3};"
        : "+f"(d[0]), "+f"(d[1]), "+f"(d[2]), "+f"(d[3])
        : "r"(a[0]), "r"(a[1]), "r"(a[2]), "r"(a[3]), "r"(b[0]), "r"(b[1]));
}

// ------------------------------ LayerNorm ----------------------------------
__global__ __launch_bounds__(256) void ln_kernel(const float* __restrict__ x,
                                                 const float* __restrict__ gamma) {
    int row = blockIdx.x;
    int tid = threadIdx.x;
    const float4* xr = (const float4*)(x + (size_t)row * DIM);
    float4* out = (float4*)(g_xn + (size_t)row * DIM);
    const float4* g4 = (const float4*)gamma;

    float s = 0.f, sq = 0.f;
    float4 v[2];
    #pragma unroll
    for (int i = 0; i < 2; i++) {
        v[i] = xr[tid + 256 * i];
        s += v[i].x + v[i].y + v[i].z + v[i].w;
        sq += v[i].x * v[i].x + v[i].y * v[i].y + v[i].z * v[i].z + v[i].w * v[i].w;
    }
    __shared__ float red[256], red2[256];
    red[tid] = s; red2[tid] = sq;
    __syncthreads();
    for (int off = 128; off > 0; off >>= 1) {
        if (tid < off) { red[tid] += red[tid + off]; red2[tid] += red2[tid + off]; }
        __syncthreads();
    }
    float mu = red[0] * (1.0f / DIM);
    float var = red2[0] * (1.0f / DIM) - mu * mu;
    float inv = rsqrtf(var + LN_EPS);
    #pragma unroll
    for (int i = 0; i < 2; i++) {
        float4 g = g4[tid + 256 * i];
        float4 o;
        o.x = tf32r((v[i].x - mu) * inv * g.x);
        o.y = tf32r((v[i].y - mu) * inv * g.y);
        o.z = tf32r((v[i].z - mu) * inv * g.z);
        o.w = tf32r((v[i].w - mu) * inv * g.w);
        out[tid + 256 * i] = o;
    }
}

// ------------------------- weight rounding (tf32) ---------------------------
__global__ __launch_bounds__(256) void round_kernel(const float4* __restrict__ src,
                                                    float4* __restrict__ dst, size_t n4) {
    for (size_t i = (size_t)blockIdx.x * 256 + threadIdx.x; i < n4;
         i += (size_t)gridDim.x * 256) {
        float4 v = src[i];
        v.x = tf32r(v.x); v.y = tf32r(v.y); v.z = tf32r(v.z); v.w = tf32r(v.w);
        dst[i] = v;
    }
}

// ------------------------- tensor-core tf32 GEMM ----------------------------
// C[M,N] (+)= alpha * A[M,K] @ B.
//  TRANSB=false: B stored [N,K] row-major (k contiguous)       -> Bs[n][k]
//  TRANSB=true : B stored [K,N] row-major (n contiguous)       -> Bs[k][n]
// blockIdx.x = M tile, blockIdx.y = N tile, blockIdx.z = batch.
// 128x128x32 tile, 4-stage cp.async pipeline, 256 threads (2x4 warps, 64x32 each).
#define ASTRIDE 36     // floats per A/Bn row (32 + 4 pad)
#define BSTRIDE 136    // floats per Bt row  (128 + 8 pad)
#define ABYTES  (128 * ASTRIDE * 4)   // 18432
#define BBYTES  18432                 // max(32*136, 128*36) * 4
#define STAGE   (ABYTES + BBYTES)     // 36864
#define NSTG    4

template <bool TRANSB, bool ACCUM, bool CAUSAL_QK, bool CAUSAL_PV, bool ROUND>
__global__ __launch_bounds__(256, 1)
void mma_gemm(const float* __restrict__ A, long long lda, long long strideA,
              const float* __restrict__ B, long long ldb, long long strideB,
              float* __restrict__ C, long long ldc, long long strideC,
              int K, float alpha)
{
    const int bx = blockIdx.x;   // m tile
    const int by = blockIdx.y;   // n tile
    const int bz = blockIdx.z;
    if (CAUSAL_QK && by > bx) return;

    A += (size_t)bz * strideA;
    B += (size_t)bz * strideB;
    C += (size_t)bz * strideC;

    const int m0 = bx * 128;
    const int n0 = by * 128;
    const int K_eff = CAUSAL_PV ? min(K, m0 + 128) : K;
    const int NT = K_eff >> 5;

    extern __shared__ char smem[];
    const uint32_t sm_u = smem_u32(smem);

    const int tid = threadIdx.x;
    const int lane = tid & 31;
    const int warp = tid >> 5;
    const int wm = warp & 1;          // 0..1  (64 rows each)
    const int wn = warp >> 1;         // 0..3  (32 cols each)
    const int g = lane >> 2;          // 0..7
    const int tig = lane & 3;         // 0..3

    // producer indices (per-thread, fixed)
    const int a_row = tid >> 3;               // 0..31 (x4 iters -> 0..127)
    const int a_c4  = tid & 7;
    const int bt_kr = tid >> 6;               // 0..3  (x4 -> 0..15? no: see below)

    float acc[4][4][4];
    #pragma unroll
    for (int i = 0; i < 4; i++)
        #pragma unroll
        for (int j = 0; j < 4; j++)
            #pragma unroll
            for (int r = 0; r < 4; r++) acc[i][j][r] = 0.f;

    auto load_stage = [&](int st, int t) {
        const uint32_t abase = sm_u + st * STAGE;
        const uint32_t bbase = abase + ABYTES;
        const long long kk = (long long)t << 5;
        // A tile: 128 x 32 floats, layout [m][k] stride 36
        #pragma unroll
        for (int i = 0; i < 4; i++) {
            int row = a_row + 32 * i;
            uint32_t so = abase + (uint32_t)(row * ASTRIDE + a_c4 * 4) * 4;
            const float* gp = A + (size_t)(m0 + row) * lda + kk + a_c4 * 4;
            CP_ASYNC16(so, gp);
        }
        if (TRANSB) {
            // B tile: 32 k-rows x 128 n, layout [k][n] stride 136
            #pragma unroll
            for (int i = 0; i < 4; i++) {
                int idx = tid + 256 * i;
                int kr = idx >> 5;           // 0..31
                int c4 = idx & 31;           // 0..31
                uint32_t so = bbase + (uint32_t)(kr * BSTRIDE + c4 * 4) * 4;
                const float* gp = B + (size_t)(kk + kr) * ldb + n0 + c4 * 4;
                CP_ASYNC16(so, gp);
            }
        } else {
            // B tile: 128 n-rows x 32 k, layout [n][k] stride 36
            #pragma unroll
            for (int i = 0; i < 4; i++) {
                int row = a_row + 32 * i;
                uint32_t so = bbase + (uint32_t)(row * ASTRIDE + a_c4 * 4) * 4;
                const float* gp = B + (size_t)(n0 + row) * ldb + kk + a_c4 * 4;
                CP_ASYNC16(so, gp);
            }
        }
    };

    // prefetch
    #pragma unroll
    for (int s = 0; s < NSTG - 1; s++) {
        if (s < NT) load_stage(s, s);
        CP_COMMIT();
    }
    CP_WAIT2();
    __syncthreads();

    for (int t = 0; t < NT; t++) {
        int lt = t + NSTG - 1;
        if (lt < NT) load_stage(lt & (NSTG - 1), lt);
        CP_COMMIT();

        const float* As = (const float*)(smem + (t & (NSTG - 1)) * STAGE);
        const float* Bs = (const float*)(smem + (t & (NSTG - 1)) * STAGE + ABYTES);

        const float* Abase = As + (wm * 64 + g) * ASTRIDE + tig;
        const float* Btb = Bs + tig * BSTRIDE + wn * 32 + g;   // TRANSB
        const float* Bnb = Bs + (wn * 32 + g) * ASTRIDE + tig; // !TRANSB

        #pragma unroll
        for (int ks = 0; ks < 4; ks++) {
            uint32_t af[4][4], bf[4][2];
            #pragma unroll
            for (int mi = 0; mi < 4; mi++) {
                const float* p = Abase + ks * 8 + mi * (16 * ASTRIDE);
                af[mi][0] = __float_as_uint(p[0]);
                af[mi][1] = __float_as_uint(p[8 * ASTRIDE]);
                af[mi][2] = __float_as_uint(p[4]);
                af[mi][3] = __float_as_uint(p[8 * ASTRIDE + 4]);
            }
            if (TRANSB) {
                const float* p = Btb + ks * 8 * BSTRIDE;
                #pragma unroll
                for (int nj = 0; nj < 4; nj++) {
                    bf[nj][0] = __float_as_uint(p[nj * 8]);
                    bf[nj][1] = __float_as_uint(p[4 * BSTRIDE + nj * 8]);
                }
            } else {
                const float* p = Bnb + ks * 8;
                #pragma unroll
                for (int nj = 0; nj < 4; nj++) {
                    bf[nj][0] = __float_as_uint(p[nj * 8 * ASTRIDE]);
                    bf[nj][1] = __float_as_uint(p[nj * 8 * ASTRIDE + 4]);
                }
            }
            #pragma unroll
            for (int mi = 0; mi < 4; mi++)
                #pragma unroll
                for (int nj = 0; nj < 4; nj++)
                    mma1688(acc[mi][nj], af[mi], bf[nj]);
        }
        CP_WAIT2();
        __syncthreads();
    }

    // epilogue
    #pragma unroll
    for (int mi = 0; mi < 4; mi++) {
        #pragma unroll
        for (int nj = 0; nj < 4; nj++) {
            int row = m0 + wm * 64 + mi * 16 + g;
            int col = n0 + wn * 32 + nj * 8 + tig * 2;
            float2 v0, v1;
            v0.x = acc[mi][nj][0] * alpha; v0.y = acc[mi][nj][1] * alpha;
            v1.x = acc[mi][nj][2] * alpha; v1.y = acc[mi][nj][3] * alpha;
            if (ROUND) {
                v0.x = tf32r(v0.x); v0.y = tf32r(v0.y);
                v1.x = tf32r(v1.x); v1.y = tf32r(v1.y);
            }
            float2* p0 = (float2*)(C + (size_t)row * ldc + col);
            float2* p1 = (float2*)(C + (size_t)(row + 8) * ldc + col);
            if (ACCUM) {
                float2 o0 = *p0, o1 = *p1;
                v0.x += o0.x; v0.y += o0.y; v1.x += o1.x; v1.y += o1.y;
            }
            *p0 = v0;
            *p1 = v1;
        }
    }
}

// ------------------------ causal softmax (in place) -------------------------
__global__ __launch_bounds__(256) void softmax_causal(void) {
    int i = blockIdx.x;       // query row
    int h = blockIdx.y;       // head
    float* row = g_sim + ((size_t)h * NSEQ + i) * NSEQ;
    int L = i + 1;
    int Lr = (L + 127) & ~127;   // PV reads k < roundup(L,128)
    int tid = threadIdx.x;

    __shared__ float red[256];

    float m = -INFINITY;
    for (int j = tid; j < L; j += 256) m = fmaxf(m, row[j]);
    red[tid] = m;
    __syncthreads();
    for (int off = 128; off > 0; off >>= 1) {
        if (tid < off) red[tid] = fmaxf(red[tid], red[tid + off]);
        __syncthreads();
    }
    m = red[0];
    __syncthreads();

    float s = 0.f;
    for (int j = tid; j < L; j += 256) {
        float e = expf(row[j] - m);
        row[j] = e;
        s += e;
    }
    red[tid] = s;
    __syncthreads();
    for (int off = 128; off > 0; off >>= 1) {
        if (tid < off) red[tid] += red[tid + off];
        __syncthreads();
    }
    float inv = 1.0f / red[0];

    for (int j = tid; j < L; j += 256) row[j] = tf32r(row[j] * inv);
    for (int j = L + tid; j < Lr; j += 256) row[j] = 0.f;
}

// --------------------------- SwiGLU activation ------------------------------
__global__ __launch_bounds__(256) void ff_act_kernel(void) {
    size_t total = (size_t)NSEQ * FF_INNER;
    for (size_t idx = (size_t)blockIdx.x * blockDim.x + threadIdx.x;
         idx < total; idx += (size_t)gridDim.x * blockDim.x) {
        size_t i = idx / FF_INNER;
        size_t j = idx % FF_INNER;
        const float* prow = g_proj + i * FUSED_OUT;
        float xv = prow[FF_BASE + j];
        float gg = prow[GATE_BASE + j];
        float sg = gg / (1.0f + expf(-gg));   // silu
        g_ffact[idx] = tf32r(sg * xv);
    }
}

// ------------------------------- launch -------------------------------------
extern "C" void kernel_launch(void* const* d_in, const int* in_sizes, int n_in,
                              void* d_out, int out_size) {
    const float* x          = (const float*)d_in[0];
    const float* gamma      = (const float*)d_in[1];
    const float* w_fused    = (const float*)d_in[2];
    const float* w_attn_out = (const float*)d_in[3];
    const float* w_ff_out   = (const float*)d_in[4];
    float* out = (float*)d_out;

    float *p_xn, *p_proj, *p_sim, *p_attnc, *p_ffact, *p_wf, *p_wao, *p_wfo;
    cudaGetSymbolAddress((void**)&p_xn, g_xn);
    cudaGetSymbolAddress((void**)&p_proj, g_proj);
    cudaGetSymbolAddress((void**)&p_sim, g_sim);
    cudaGetSymbolAddress((void**)&p_attnc, g_attnc);
    cudaGetSymbolAddress((void**)&p_ffact, g_ffact);
    cudaGetSymbolAddress((void**)&p_wf, g_wf);
    cudaGetSymbolAddress((void**)&p_wao, g_wao);
    cudaGetSymbolAddress((void**)&p_wfo, g_wfo);

    const int SMEM_DYN = NSTG * STAGE;   // 147456 B
    cudaFuncSetAttribute((const void*)mma_gemm<true,  false, false, false, true>,
                         cudaFuncAttributeMaxDynamicSharedMemorySize, SMEM_DYN);
    cudaFuncSetAttribute((const void*)mma_gemm<false, false, true,  false, false>,
                         cudaFuncAttributeMaxDynamicSharedMemorySize, SMEM_DYN);
    cudaFuncSetAttribute((const void*)mma_gemm<true,  false, false, true,  true>,
                         cudaFuncAttributeMaxDynamicSharedMemorySize, SMEM_DYN);
    cudaFuncSetAttribute((const void*)mma_gemm<true,  false, false, false, false>,
                         cudaFuncAttributeMaxDynamicSharedMemorySize, SMEM_DYN);
    cudaFuncSetAttribute((const void*)mma_gemm<true,  true,  false, false, false>,
                         cudaFuncAttributeMaxDynamicSharedMemorySize, SMEM_DYN);

    const float scale = 0.08838834764831845f;  // 128^-0.5

    // 0. round weights to tf32 (RNA) once per replay
    round_kernel<<<2048, 256>>>((const float4*)w_fused, (float4*)p_wf,
                                (size_t)DIM * FUSED_OUT / 4);
    round_kernel<<<1024, 256>>>((const float4*)w_attn_out, (float4*)p_wao,
                                (size_t)ATTN_INNER * DIM / 4);
    round_kernel<<<1024, 256>>>((const float4*)w_ff_out, (float4*)p_wfo,
                                (size_t)FF_INNER * DIM / 4);

    // 1. LayerNorm (tf32-rounded output)
    ln_kernel<<<NSEQ, 256>>>(x, gamma);

    // 2. proj = xn @ w_fused  [2048x2048]x[2048x18688], rounded output
    mma_gemm<true, false, false, false, true>
        <<<dim3(NSEQ / 128, FUSED_OUT / 128, 1), 256, SMEM_DYN>>>(
        p_xn, DIM, 0, p_wf, FUSED_OUT, 0, p_proj, FUSED_OUT, 0, DIM, 1.0f);

    // 3. sim_h = scale * Q_h @ K^T  (K matrix is [N,dh] k-contiguous -> !TRANSB)
    mma_gemm<false, false, true, false, false>
        <<<dim3(NSEQ / 128, NSEQ / 128, HEADS), 256, SMEM_DYN>>>(
        p_proj, FUSED_OUT, DH,
        p_proj + ATTN_INNER, FUSED_OUT, 0,
        p_sim, NSEQ, (long long)NSEQ * NSEQ, DH, scale);

    // 4. causal softmax (rounded P, zero-fill to 128 boundary)
    softmax_causal<<<dim3(NSEQ, HEADS), 256>>>();

    // 5. attn_h = P_h @ V  (V is [seq, dh] n-contiguous -> TRANSB), rounded output
    mma_gemm<true, false, false, true, true>
        <<<dim3(NSEQ / 128, 1, HEADS), 256, SMEM_DYN>>>(
        p_sim, NSEQ, (long long)NSEQ * NSEQ,
        p_proj + ATTN_INNER + DH, FUSED_OUT, 0,
        p_attnc, ATTN_INNER, DH, NSEQ, 1.0f);

    // 6. SwiGLU (rounded output)
    ff_act_kernel<<<2048, 256>>>();

    // 7. out = attnc @ w_attn_out
    mma_gemm<true, false, false, false, false>
        <<<dim3(NSEQ / 128, DIM / 128, 1), 256, SMEM_DYN>>>(
        p_attnc, ATTN_INNER, 0, p_wao, DIM, 0, out, DIM, 0, ATTN_INNER, 1.0f);

    // 8. out += ffact @ w_ff_out
    mma_gemm<true, true, false, false, false>
        <<<dim3(NSEQ / 128, DIM / 128, 1), 256, SMEM_DYN>>>(
        p_ffact, FF_INNER, 0, p_wfo, DIM, 0, out, DIM, 0, FF_INNER, 1.0f);
}

// round 6
// speedup vs baseline: 5.1904x; 1.1791x over previous
#include <cuda_runtime.h>
#include <cuda_bf16.h>
#include <cstdint>
#include <math.h>

// ---------------------------------------------------------------------------
// ParallelTransformerBlock via legacy tensor-core path (mma.sync tf32 + cp.async)
// B=1, N=2048, DIM=2048, HEADS=16, DH=128, FF_INNER=8192, FUSED_OUT=18688
// R6: 256x128x32 tiles, 4x2 warp grid (64x64 warp tiles), 3-stage pipeline.
// ---------------------------------------------------------------------------

#define NSEQ 2048
#define DIM 2048
#define DH 128
#define HEADS 16
#define ATTN_INNER 2048
#define FF_INNER 8192
#define FUSED_OUT 18688
#define FF_BASE 2304      // ATTN_INNER + 2*DH
#define GATE_BASE 10496   // FF_BASE + FF_INNER
#define LN_EPS 1e-5f

// ------------------------- device scratch (static) -------------------------
__device__ float g_xn[(size_t)NSEQ * DIM];                    // 16 MB
__device__ float g_proj[(size_t)NSEQ * FUSED_OUT];            // 153 MB
__device__ float g_sim[(size_t)HEADS * NSEQ * NSEQ];          // 256 MB
__device__ float g_attnc[(size_t)NSEQ * ATTN_INNER];          // 16 MB
__device__ float g_ffact[(size_t)NSEQ * FF_INNER];            // 64 MB
// tf32-rounded weight copies
__device__ float g_wf[(size_t)DIM * FUSED_OUT];               // 153 MB
__device__ float g_wao[(size_t)ATTN_INNER * DIM];             // 16 MB
__device__ float g_wfo[(size_t)FF_INNER * DIM];               // 64 MB

// --------------------------- PTX helpers -----------------------------------
__device__ __forceinline__ uint32_t smem_u32(const void* p) {
    uint32_t a;
    asm("{ .reg .u64 t; cvta.to.shared.u64 t, %1; cvt.u32.u64 %0, t; }"
        : "=r"(a) : "l"(p));
    return a;
}

__device__ __forceinline__ float tf32r(float x) {
    uint32_t u;
    asm("cvt.rna.tf32.f32 %0, %1;" : "=r"(u) : "f"(x));
    return __uint_as_float(u);
}

#define CP_ASYNC16(smaddr, gptr) \
    asm volatile("cp.async.cg.shared.global [%0], [%1], 16;" :: "r"(smaddr), "l"(gptr))
#define CP_COMMIT() asm volatile("cp.async.commit_group;" ::: "memory")
#define CP_WAIT1()  asm volatile("cp.async.wait_group 1;" ::: "memory")

__device__ __forceinline__ void mma1688(float* d, const uint32_t* a, const uint32_t* b) {
    asm volatile(
        "mma.sync.aligned.m16n8k8.row.col.f32.tf32.tf32.f32 "
        "{%0,%1,%2,%3}, {%4,%5,%6,%7}, {%8,%9}, {%0,%1,%2,%3};"
        : "+f"(d[0]), "+f"(d[1]), "+f"(d[2]), "+f"(d[3])
        : "r"(a[0]), "r"(a[1]), "r"(a[2]), "r"(a[3]), "r"(b[0]), "r"(b[1]));
}

// ------------------------------ LayerNorm ----------------------------------
__global__ __launch_bounds__(256) void ln_kernel(const float* __restrict__ x,
                                                 const float* __restrict__ gamma) {
    int row = blockIdx.x;
    int tid = threadIdx.x;
    const float4* xr = (const float4*)(x + (size_t)row * DIM);
    float4* out = (float4*)(g_xn + (size_t)row * DIM);
    const float4* g4 = (const float4*)gamma;

    float s = 0.f, sq = 0.f;
    float4 v[2];
    #pragma unroll
    for (int i = 0; i < 2; i++) {
        v[i] = xr[tid + 256 * i];
        s += v[i].x + v[i].y + v[i].z + v[i].w;
        sq += v[i].x * v[i].x + v[i].y * v[i].y + v[i].z * v[i].z + v[i].w * v[i].w;
    }
    __shared__ float red[256], red2[256];
    red[tid] = s; red2[tid] = sq;
    __syncthreads();
    for (int off = 128; off > 0; off >>= 1) {
        if (tid < off) { red[tid] += red[tid + off]; red2[tid] += red2[tid + off]; }
        __syncthreads();
    }
    float mu = red[0] * (1.0f / DIM);
    float var = red2[0] * (1.0f / DIM) - mu * mu;
    float inv = rsqrtf(var + LN_EPS);
    #pragma unroll
    for (int i = 0; i < 2; i++) {
        float4 g = g4[tid + 256 * i];
        float4 o;
        o.x = tf32r((v[i].x - mu) * inv * g.x);
        o.y = tf32r((v[i].y - mu) * inv * g.y);
        o.z = tf32r((v[i].z - mu) * inv * g.z);
        o.w = tf32r((v[i].w - mu) * inv * g.w);
        out[tid + 256 * i] = o;
    }
}

// ------------------------- weight rounding (tf32) ---------------------------
__global__ __launch_bounds__(256) void round_kernel(const float4* __restrict__ src,
                                                    float4* __restrict__ dst, size_t n4) {
    for (size_t i = (size_t)blockIdx.x * 256 + threadIdx.x; i < n4;
         i += (size_t)gridDim.x * 256) {
        float4 v = src[i];
        v.x = tf32r(v.x); v.y = tf32r(v.y); v.z = tf32r(v.z); v.w = tf32r(v.w);
        dst[i] = v;
    }
}

// ------------------------- tensor-core tf32 GEMM ----------------------------
// C[M,N] (+)= alpha * A[M,K] @ B.
//  TRANSB=false: B stored [N,K] row-major (k contiguous)  -> Bs[n][k]
//  TRANSB=true : B stored [K,N] row-major (n contiguous)  -> Bs[k][n]
// blockIdx.x = M tile (256 rows), blockIdx.y = N tile (128 cols), z = batch.
// 256x128x32 CTA tile, 3-stage cp.async, 256 threads: 8 warps 4(m) x 2(n),
// each warp 64x64 (4x8 m16n8k8 fragments).
#define ASTRIDE 36     // floats per A/Bn row (32 + 4 pad)
#define BSTRIDE 136    // floats per Bt row  (128 + 8 pad)
#define ABYTES  (256 * ASTRIDE * 4)   // 36864
#define BBYTES  18432                 // max(32*136, 128*36) * 4
#define STAGE   (ABYTES + BBYTES)     // 55296
#define NSTG    3

template <bool TRANSB, bool ACCUM, bool CAUSAL_QK, bool CAUSAL_PV, bool ROUND>
__global__ __launch_bounds__(256, 1)
void mma_gemm(const float* __restrict__ A, long long lda, long long strideA,
              const float* __restrict__ B, long long ldb, long long strideB,
              float* __restrict__ C, long long ldc, long long strideC,
              int K, float alpha)
{
    const int bx = blockIdx.x;   // m tile
    const int by = blockIdx.y;   // n tile
    const int bz = blockIdx.z;
    if (CAUSAL_QK && by > 2 * bx + 1) return;   // tile fully above diagonal

    A += (size_t)bz * strideA;
    B += (size_t)bz * strideB;
    C += (size_t)bz * strideC;

    const int m0 = bx * 256;
    const int n0 = by * 128;
    const int K_eff = CAUSAL_PV ? min(K, m0 + 256) : K;
    const int NT = K_eff >> 5;

    extern __shared__ char smem[];
    const uint32_t sm_u = smem_u32(smem);

    const int tid = threadIdx.x;
    const int lane = tid & 31;
    const int warp = tid >> 5;
    const int wm = warp & 3;          // 0..3  (64 rows each)
    const int wn = warp >> 2;         // 0..1  (64 cols each)
    const int g = lane >> 2;          // 0..7
    const int tig = lane & 3;         // 0..3

    // producer indices
    const int a_row = tid >> 3;       // 0..31
    const int a_c4  = tid & 7;

    float acc[4][8][4];
    #pragma unroll
    for (int i = 0; i < 4; i++)
        #pragma unroll
        for (int j = 0; j < 8; j++)
            #pragma unroll
            for (int r = 0; r < 4; r++) acc[i][j][r] = 0.f;

    auto load_stage = [&](int st, int t) {
        const uint32_t abase = sm_u + st * STAGE;
        const uint32_t bbase = abase + ABYTES;
        const long long kk = (long long)t << 5;
        // A tile: 256 rows x 32 floats, layout [m][k] stride 36
        #pragma unroll
        for (int i = 0; i < 8; i++) {
            int row = a_row + 32 * i;
            uint32_t so = abase + (uint32_t)(row * ASTRIDE + a_c4 * 4) * 4;
            const float* gp = A + (size_t)(m0 + row) * lda + kk + a_c4 * 4;
            CP_ASYNC16(so, gp);
        }
        if (TRANSB) {
            // B tile: 32 k-rows x 128 n, layout [k][n] stride 136
            #pragma unroll
            for (int i = 0; i < 4; i++) {
                int idx = tid + 256 * i;
                int kr = idx >> 5;           // 0..31
                int c4 = idx & 31;           // 0..31
                uint32_t so = bbase + (uint32_t)(kr * BSTRIDE + c4 * 4) * 4;
                const float* gp = B + (size_t)(kk + kr) * ldb + n0 + c4 * 4;
                CP_ASYNC16(so, gp);
            }
        } else {
            // B tile: 128 n-rows x 32 k, layout [n][k] stride 36
            #pragma unroll
            for (int i = 0; i < 4; i++) {
                int row = a_row + 32 * i;
                uint32_t so = bbase + (uint32_t)(row * ASTRIDE + a_c4 * 4) * 4;
                const float* gp = B + (size_t)(n0 + row) * ldb + kk + a_c4 * 4;
                CP_ASYNC16(so, gp);
            }
        }
    };

    // prefetch 2 stages
    #pragma unroll
    for (int s = 0; s < NSTG - 1; s++) {
        if (s < NT) load_stage(s, s);
        CP_COMMIT();
    }
    CP_WAIT1();
    __syncthreads();

    int st = 0;                        // stage of chunk t
    for (int t = 0; t < NT; t++) {
        int lt = t + NSTG - 1;
        int lst = st + NSTG - 1; if (lst >= NSTG) lst -= NSTG;
        if (lt < NT) load_stage(lst, lt);
        CP_COMMIT();

        const float* As = (const float*)(smem + st * STAGE);
        const float* Bs = (const float*)(smem + st * STAGE + ABYTES);

        const float* Abase = As + (wm * 64 + g) * ASTRIDE + tig;
        const float* Btb = Bs + tig * BSTRIDE + wn * 64 + g;   // TRANSB
        const float* Bnb = Bs + (wn * 64 + g) * ASTRIDE + tig; // !TRANSB

        #pragma unroll
        for (int ks = 0; ks < 4; ks++) {
            uint32_t af[4][4], bf[8][2];
            #pragma unroll
            for (int mi = 0; mi < 4; mi++) {
                const float* p = Abase + ks * 8 + mi * (16 * ASTRIDE);
                af[mi][0] = __float_as_uint(p[0]);
                af[mi][1] = __float_as_uint(p[8 * ASTRIDE]);
                af[mi][2] = __float_as_uint(p[4]);
                af[mi][3] = __float_as_uint(p[8 * ASTRIDE + 4]);
            }
            if (TRANSB) {
                const float* p = Btb + ks * 8 * BSTRIDE;
                #pragma unroll
                for (int nj = 0; nj < 8; nj++) {
                    bf[nj][0] = __float_as_uint(p[nj * 8]);
                    bf[nj][1] = __float_as_uint(p[4 * BSTRIDE + nj * 8]);
                }
            } else {
                const float* p = Bnb + ks * 8;
                #pragma unroll
                for (int nj = 0; nj < 8; nj++) {
                    bf[nj][0] = __float_as_uint(p[nj * 8 * ASTRIDE]);
                    bf[nj][1] = __float_as_uint(p[nj * 8 * ASTRIDE + 4]);
                }
            }
            #pragma unroll
            for (int mi = 0; mi < 4; mi++)
                #pragma unroll
                for (int nj = 0; nj < 8; nj++)
                    mma1688(acc[mi][nj], af[mi], bf[nj]);
        }
        CP_WAIT1();
        __syncthreads();
        if (++st == NSTG) st = 0;
    }

    // epilogue
    #pragma unroll
    for (int mi = 0; mi < 4; mi++) {
        #pragma unroll
        for (int nj = 0; nj < 8; nj++) {
            int row = m0 + wm * 64 + mi * 16 + g;
            int col = n0 + wn * 64 + nj * 8 + tig * 2;
            float2 v0, v1;
            v0.x = acc[mi][nj][0] * alpha; v0.y = acc[mi][nj][1] * alpha;
            v1.x = acc[mi][nj][2] * alpha; v1.y = acc[mi][nj][3] * alpha;
            if (ROUND) {
                v0.x = tf32r(v0.x); v0.y = tf32r(v0.y);
                v1.x = tf32r(v1.x); v1.y = tf32r(v1.y);
            }
            float2* p0 = (float2*)(C + (size_t)row * ldc + col);
            float2* p1 = (float2*)(C + (size_t)(row + 8) * ldc + col);
            if (ACCUM) {
                float2 o0 = *p0, o1 = *p1;
                v0.x += o0.x; v0.y += o0.y; v1.x += o1.x; v1.y += o1.y;
            }
            *p0 = v0;
            *p1 = v1;
        }
    }
}

// ------------------------ causal softmax (in place) -------------------------
// PV GEMM uses 256-row M tiles and reads k < m0+256; zero-fill to 256 boundary.
__global__ __launch_bounds__(256) void softmax_causal(void) {
    int i = blockIdx.x;       // query row
    int h = blockIdx.y;       // head
    float* row = g_sim + ((size_t)h * NSEQ + i) * NSEQ;
    float4* row4 = (float4*)row;
    int L = i + 1;
    int Lr = (L + 255) & ~255;
    int nv = L >> 2;          // full float4s
    int tid = threadIdx.x;

    __shared__ float red[256];

    float m = -INFINITY;
    for (int j = tid; j < nv; j += 256) {
        float4 v = row4[j];
        m = fmaxf(m, fmaxf(fmaxf(v.x, v.y), fmaxf(v.z, v.w)));
    }
    for (int j = (nv << 2) + tid; j < L; j += 256) m = fmaxf(m, row[j]);
    red[tid] = m;
    __syncthreads();
    for (int off = 128; off > 0; off >>= 1) {
        if (tid < off) red[tid] = fmaxf(red[tid], red[tid + off]);
        __syncthreads();
    }
    m = red[0];
    __syncthreads();

    float s = 0.f;
    for (int j = tid; j < nv; j += 256) {
        float4 v = row4[j];
        v.x = expf(v.x - m); v.y = expf(v.y - m);
        v.z = expf(v.z - m); v.w = expf(v.w - m);
        row4[j] = v;
        s += v.x + v.y + v.z + v.w;
    }
    for (int j = (nv << 2) + tid; j < L; j += 256) {
        float e = expf(row[j] - m);
        row[j] = e;
        s += e;
    }
    red[tid] = s;
    __syncthreads();
    for (int off = 128; off > 0; off >>= 1) {
        if (tid < off) red[tid] += red[tid + off];
        __syncthreads();
    }
    float inv = 1.0f / red[0];

    for (int j = tid; j < nv; j += 256) {
        float4 v = row4[j];
        v.x = tf32r(v.x * inv); v.y = tf32r(v.y * inv);
        v.z = tf32r(v.z * inv); v.w = tf32r(v.w * inv);
        row4[j] = v;
    }
    for (int j = (nv << 2) + tid; j < L; j += 256) row[j] = tf32r(row[j] * inv);
    for (int j = L + tid; j < Lr; j += 256) row[j] = 0.f;
}

// --------------------------- SwiGLU activation ------------------------------
__global__ __launch_bounds__(256) void ff_act_kernel(void) {
    int row = blockIdx.y;
    int j4 = blockIdx.x * 256 + threadIdx.x;       // 0..2047 (float4 index)
    const float* prow = g_proj + (size_t)row * FUSED_OUT;
    float4 xv = *(const float4*)(prow + FF_BASE + j4 * 4);
    float4 gg = *(const float4*)(prow + GATE_BASE + j4 * 4);
    float4 o;
    o.x = tf32r(xv.x * (gg.x / (1.0f + expf(-gg.x))));
    o.y = tf32r(xv.y * (gg.y / (1.0f + expf(-gg.y))));
    o.z = tf32r(xv.z * (gg.z / (1.0f + expf(-gg.z))));
    o.w = tf32r(xv.w * (gg.w / (1.0f + expf(-gg.w))));
    *(float4*)(g_ffact + (size_t)row * FF_INNER + j4 * 4) = o;
}

// ------------------------------- launch -------------------------------------
extern "C" void kernel_launch(void* const* d_in, const int* in_sizes, int n_in,
                              void* d_out, int out_size) {
    const float* x          = (const float*)d_in[0];
    const float* gamma      = (const float*)d_in[1];
    const float* w_fused    = (const float*)d_in[2];
    const float* w_attn_out = (const float*)d_in[3];
    const float* w_ff_out   = (const float*)d_in[4];
    float* out = (float*)d_out;

    float *p_xn, *p_proj, *p_sim, *p_attnc, *p_ffact, *p_wf, *p_wao, *p_wfo;
    cudaGetSymbolAddress((void**)&p_xn, g_xn);
    cudaGetSymbolAddress((void**)&p_proj, g_proj);
    cudaGetSymbolAddress((void**)&p_sim, g_sim);
    cudaGetSymbolAddress((void**)&p_attnc, g_attnc);
    cudaGetSymbolAddress((void**)&p_ffact, g_ffact);
    cudaGetSymbolAddress((void**)&p_wf, g_wf);
    cudaGetSymbolAddress((void**)&p_wao, g_wao);
    cudaGetSymbolAddress((void**)&p_wfo, g_wfo);

    const int SMEM_DYN = NSTG * STAGE;   // 165888 B
    cudaFuncSetAttribute((const void*)mma_gemm<true,  false, false, false, true>,
                         cudaFuncAttributeMaxDynamicSharedMemorySize, SMEM_DYN);
    cudaFuncSetAttribute((const void*)mma_gemm<false, false, true,  false, false>,
                         cudaFuncAttributeMaxDynamicSharedMemorySize, SMEM_DYN);
    cudaFuncSetAttribute((const void*)mma_gemm<true,  false, false, true,  true>,
                         cudaFuncAttributeMaxDynamicSharedMemorySize, SMEM_DYN);
    cudaFuncSetAttribute((const void*)mma_gemm<true,  false, false, false, false>,
                         cudaFuncAttributeMaxDynamicSharedMemorySize, SMEM_DYN);
    cudaFuncSetAttribute((const void*)mma_gemm<true,  true,  false, false, false>,
                         cudaFuncAttributeMaxDynamicSharedMemorySize, SMEM_DYN);

    const float scale = 0.08838834764831845f;  // 128^-0.5

    // 0. round weights to tf32 (RNA)
    round_kernel<<<2048, 256>>>((const float4*)w_fused, (float4*)p_wf,
                                (size_t)DIM * FUSED_OUT / 4);
    round_kernel<<<1024, 256>>>((const float4*)w_attn_out, (float4*)p_wao,
                                (size_t)ATTN_INNER * DIM / 4);
    round_kernel<<<1024, 256>>>((const float4*)w_ff_out, (float4*)p_wfo,
                                (size_t)FF_INNER * DIM / 4);

    // 1. LayerNorm (tf32-rounded output)
    ln_kernel<<<NSEQ, 256>>>(x, gamma);

    // 2. proj = xn @ w_fused  [2048x2048]x[2048x18688]
    mma_gemm<true, false, false, false, true>
        <<<dim3(NSEQ / 256, FUSED_OUT / 128, 1), 256, SMEM_DYN>>>(
        p_xn, DIM, 0, p_wf, FUSED_OUT, 0, p_proj, FUSED_OUT, 0, DIM, 1.0f);

    // 3. sim_h = scale * Q_h @ K^T  (K matrix [N,dh] k-contiguous -> !TRANSB)
    mma_gemm<false, false, true, false, false>
        <<<dim3(NSEQ / 256, NSEQ / 128, HEADS), 256, SMEM_DYN>>>(
        p_proj, FUSED_OUT, DH,
        p_proj + ATTN_INNER, FUSED_OUT, 0,
        p_sim, NSEQ, (long long)NSEQ * NSEQ, DH, scale);

    // 4. causal softmax (zero-fill to 256 boundary)
    softmax_causal<<<dim3(NSEQ, HEADS), 256>>>();

    // 5. attn_h = P_h @ V  (V [seq, dh] n-contiguous -> TRANSB, K clipped)
    mma_gemm<true, false, false, true, true>
        <<<dim3(NSEQ / 256, 1, HEADS), 256, SMEM_DYN>>>(
        p_sim, NSEQ, (long long)NSEQ * NSEQ,
        p_proj + ATTN_INNER + DH, FUSED_OUT, 0,
        p_attnc, ATTN_INNER, DH, NSEQ, 1.0f);

    // 6. SwiGLU
    ff_act_kernel<<<dim3(FF_INNER / 1024, NSEQ), 256>>>();

    // 7. out = attnc @ w_attn_out
    mma_gemm<true, false, false, false, false>
        <<<dim3(NSEQ / 256, DIM / 128, 1), 256, SMEM_DYN>>>(
        p_attnc, ATTN_INNER, 0, p_wao, DIM, 0, out, DIM, 0, ATTN_INNER, 1.0f);

    // 8. out += ffact @ w_ff_out
    mma_gemm<true, true, false, false, false>
        <<<dim3(NSEQ / 256, DIM / 128, 1), 256, SMEM_DYN>>>(
        p_ffact, FF_INNER, 0, p_wfo, DIM, 0, out, DIM, 0, FF_INNER, 1.0f);
}